// round 16
// baseline (speedup 1.0000x reference)
#include <cuda_runtime.h>

#define BB 16
#define NN 1024
#define DD 32
#define BN (BB*NN)
#define NBLK 148
#define TPB 256
#define L2E 1.4426950408889634f
#define LN2F 0.6931471805599453f
#define EPSF 0.1f
#define SFQ 0.5625f
#define THR 0.001f
#define LOGNF 6.9314718055994531f

__device__ float d_C[(size_t)BB*NN*NN];
__device__ float d_sx[BB*NN*DD];
__device__ float d_x2[BN];
__device__ float d_logw[BN];
__device__ float d_eps0[BB];
__device__ float d_ay[BN], d_bx[BN], d_ga[BN], d_gb[BN], d_alpha[BN];
__device__ float d_res[BN*DD];
__device__ unsigned d_dmax[2][2*BB];
__device__ unsigned d_barcnt;
__device__ volatile unsigned d_bargen;

__device__ __forceinline__ float ex2(float x){ float r; asm("ex2.approx.ftz.f32 %0,%1;":"=f"(r):"f"(x)); return r; }
__device__ __forceinline__ float lg2(float x){ float r; asm("lg2.approx.f32 %0,%1;":"=f"(r):"f"(x)); return r; }

__device__ __forceinline__ void gsync(){
    __syncthreads();
    __threadfence();
    if (threadIdx.x == 0){
        unsigned gen = d_bargen;
        if (atomicAdd(&d_barcnt, 1u) == NBLK-1){
            d_barcnt = 0;
            __threadfence();
            d_bargen = gen + 1;
        } else {
            while (d_bargen == gen) __nanosleep(64);
        }
    }
    __syncthreads();
    __threadfence();
}

__device__ __forceinline__ void load_t(float* t, const float4* row4, int lane, float cs){
#pragma unroll
    for (int u = 0; u < 8; u++){
        float4 v = row4[u*32 + lane];
        t[u*4+0]=v.x*cs; t[u*4+1]=v.y*cs; t[u*4+2]=v.z*cs; t[u*4+3]=v.w*cs;
    }
}

// log2-domain lse over j of (g[j] + t[j]) for one row (warp-collective)
__device__ __forceinline__ float lse2(const float* t, const float4* g4, int lane){
    float v[32];
#pragma unroll
    for (int u = 0; u < 8; u++){
        float4 g = g4[u*32 + lane];
        v[u*4+0]=g.x+t[u*4+0]; v[u*4+1]=g.y+t[u*4+1];
        v[u*4+2]=g.z+t[u*4+2]; v[u*4+3]=g.w+t[u*4+3];
    }
    float m = -1e30f;
#pragma unroll
    for (int q = 0; q < 32; q++) m = fmaxf(m, v[q]);
#pragma unroll
    for (int o = 16; o; o >>= 1) m = fmaxf(m, __shfl_xor_sync(0xffffffffu, m, o));
    float s = 0.f;
#pragma unroll
    for (int q = 0; q < 32; q++) s += ex2(v[q] - m);
#pragma unroll
    for (int o = 16; o; o >>= 1) s += __shfl_xor_sync(0xffffffffu, s, o);
    return m + lg2(s);
}

__device__ __forceinline__ float lse2c(const float* t, int lane){
    float m = -1e30f;
#pragma unroll
    for (int q = 0; q < 32; q++) m = fmaxf(m, t[q]);
#pragma unroll
    for (int o = 16; o; o >>= 1) m = fmaxf(m, __shfl_xor_sync(0xffffffffu, m, o));
    float s = 0.f;
#pragma unroll
    for (int q = 0; q < 32; q++) s += ex2(t[q] - m);
#pragma unroll
    for (int o = 16; o; o >>= 1) s += __shfl_xor_sync(0xffffffffu, s, o);
    return m + lg2(s);
}

// ---------------- K1: per-batch stats, sx, x2, logw, eps0 -------------------
__global__ void k_stats(const float* __restrict__ P, const float* __restrict__ W){
    int b = blockIdx.x, tid = threadIdx.x;
    int d = tid & 31, g = tid >> 5;
    const float* Pb = P + (size_t)b*NN*DD;
    __shared__ float red[8][32];
    __shared__ float mean[32];
    __shared__ float s_inv;
    __shared__ float gmx[8], gmn[8];

    float s = 0.f;
    for (int n = g; n < NN; n += 8) s += Pb[n*DD + d];
    red[g][d] = s; __syncthreads();
    if (g == 0){
        float t = 0.f;
        for (int i = 0; i < 8; i++) t += red[i][d];
        mean[d] = t * (1.f/NN);
    }
    __syncthreads();
    float mu = mean[d];
    float q = 0.f;
    for (int n = g; n < NN; n += 8){ float c = Pb[n*DD+d]-mu; q += c*c; }
    __syncthreads();
    red[g][d] = q; __syncthreads();
    if (tid < 32){
        float t = 0.f;
        for (int i = 0; i < 8; i++) t += red[i][tid];
        float sd = sqrtf(t * (1.f/NN));
        for (int o = 16; o; o >>= 1) sd = fmaxf(sd, __shfl_xor_sync(0xffffffffu, sd, o));
        if (tid == 0){
            float diam = (sd == 0.f) ? 1.f : sd;
            s_inv = 1.f/(diam * sqrtf(32.f));
        }
    }
    __syncthreads();
    float inv = s_inv;
    float mx = -1e30f, mn = 1e30f;
    for (int n = g; n < NN; n += 8){
        float sx = (Pb[n*DD+d]-mu)*inv;
        d_sx[((size_t)b*NN+n)*DD + d] = sx;
        mx = fmaxf(mx, sx); mn = fminf(mn, sx);
        float sq = sx*sx;
        for (int o = 16; o; o >>= 1) sq += __shfl_xor_sync(0xffffffffu, sq, o);
        if (d == 0) d_x2[b*NN+n] = sq;
    }
    for (int o = 16; o; o >>= 1){
        mx = fmaxf(mx, __shfl_xor_sync(0xffffffffu, mx, o));
        mn = fminf(mn, __shfl_xor_sync(0xffffffffu, mn, o));
    }
    if (d == 0){ gmx[g] = mx; gmn[g] = mn; }
    __syncthreads();
    if (tid == 0){
        float a = gmx[0], c = gmn[0];
        for (int i = 1; i < 8; i++){ a = fmaxf(a,gmx[i]); c = fminf(c,gmn[i]); }
        float d2 = a - c;
        d_eps0[b] = d2*d2;
    }
    for (int i = tid; i < NN; i += TPB) d_logw[b*NN+i] = logf(W[b*NN+i]);
}

// ---------------- K2: cost matrix (64x64 tiles) -----------------------------
__global__ void k_cost(){
    int b = blockIdx.z, ti = blockIdx.y*64, tj = blockIdx.x*64;
    __shared__ float As[64][33], Bs[64][33];
    __shared__ float Ax2[64], Bx2[64];
    int tid = threadIdx.x;
    const float* Sb = d_sx + (size_t)b*NN*DD;
    for (int f = tid; f < 512; f += TPB){
        int row = f >> 3, c4 = f & 7;
        float4 va = ((const float4*)(Sb + (size_t)(ti+row)*DD))[c4];
        As[row][c4*4+0]=va.x; As[row][c4*4+1]=va.y; As[row][c4*4+2]=va.z; As[row][c4*4+3]=va.w;
        float4 vb = ((const float4*)(Sb + (size_t)(tj+row)*DD))[c4];
        Bs[row][c4*4+0]=vb.x; Bs[row][c4*4+1]=vb.y; Bs[row][c4*4+2]=vb.z; Bs[row][c4*4+3]=vb.w;
    }
    if (tid < 64){ Ax2[tid] = d_x2[b*NN+ti+tid]; Bx2[tid] = d_x2[b*NN+tj+tid]; }
    __syncthreads();
    int tx = tid & 15, ty = tid >> 4;
    int i0 = ty*4, j0 = tx*4;
    float acc[4][4] = {};
#pragma unroll
    for (int k = 0; k < 32; k++){
        float a0=As[i0+0][k], a1=As[i0+1][k], a2=As[i0+2][k], a3=As[i0+3][k];
        float b0=Bs[j0+0][k], b1=Bs[j0+1][k], b2=Bs[j0+2][k], b3=Bs[j0+3][k];
        acc[0][0]+=a0*b0; acc[0][1]+=a0*b1; acc[0][2]+=a0*b2; acc[0][3]+=a0*b3;
        acc[1][0]+=a1*b0; acc[1][1]+=a1*b1; acc[1][2]+=a1*b2; acc[1][3]+=a1*b3;
        acc[2][0]+=a2*b0; acc[2][1]+=a2*b1; acc[2][2]+=a2*b2; acc[2][3]+=a2*b3;
        acc[3][0]+=a3*b0; acc[3][1]+=a3*b1; acc[3][2]+=a3*b2; acc[3][3]+=a3*b3;
    }
#pragma unroll
    for (int ii = 0; ii < 4; ii++){
        float xi = Ax2[i0+ii];
        float4 o;
        o.x = 0.5f*fmaxf(xi + Bx2[j0+0] - 2.f*acc[ii][0], 0.f);
        o.y = 0.5f*fmaxf(xi + Bx2[j0+1] - 2.f*acc[ii][1], 0.f);
        o.z = 0.5f*fmaxf(xi + Bx2[j0+2] - 2.f*acc[ii][2], 0.f);
        o.w = 0.5f*fmaxf(xi + Bx2[j0+3] - 2.f*acc[ii][3], 0.f);
        *(float4*)(d_C + ((size_t)(b*NN) + ti + i0 + ii)*NN + tj + j0) = o;
    }
}

// ---------------- K3: persistent Sinkhorn ----------------------------------
__global__ void __launch_bounds__(TPB) k_sink(){
    __shared__ float s_eps[BB];
    __shared__ int s_glob[BB];
    __shared__ int s_stop;
    int tid = threadIdx.x, lane = tid & 31;
    int gw = blockIdx.x*8 + (tid >> 5);
    const int GW = NBLK*8;
    const int GT = NBLK*TPB;

    if (tid < BB) s_eps[tid] = d_eps0[tid];
    __syncthreads();

    for (int i = blockIdx.x*TPB+tid; i < BN; i += GT) d_ga[i] = d_logw[i]*L2E;
    gsync();
    for (int r = gw; r < BN; r += GW){
        int b = r >> 10;
        float eps = s_eps[b];
        float t[32];
        load_t(t, (const float4*)(d_C + ((size_t)r<<10)), lane, -L2E/eps);
        float l1 = lse2(t, (const float4*)(d_ga + (b<<10)), lane);
        float l2 = lse2c(t, lane) - 10.0f;
        if (lane == 0){ d_ay[r] = -eps*LN2F*l1; d_bx[r] = -eps*LN2F*l2; }
    }
    gsync();

    for (int it = 0; it < 99; ++it){
        if (it > 0){
            if (tid < BB){
                int pp = (it-1) & 1;
                float da = __uint_as_float(d_dmax[pp][tid]);
                float db = __uint_as_float(d_dmax[pp][BB+tid]);
                float re = s_eps[tid];
                float ne = fmaxf(re*SFQ, EPSF);
                s_glob[tid] = (ne < re) || (da > THR) || (db > THR);
                s_eps[tid] = ne;
            }
            __syncthreads();
            if (tid == 0){
                int st = 0;
                for (int i = 0; i < BB; i++) if (!s_glob[i]) st = 1;
                s_stop = st;
            }
            __syncthreads();
            if (s_stop) break;
        }
        if (blockIdx.x == 0 && tid < 2*BB) d_dmax[it&1][tid] = 0u;
        for (int i = blockIdx.x*TPB+tid; i < BN; i += GT){
            int b = i >> 10;
            float ir = 1.f/s_eps[b];
            d_ga[i] = (d_logw[i] + d_bx[i]*ir)*L2E;
            d_gb[i] = (d_ay[i]*ir)*L2E - 10.0f;
        }
        gsync();
        int p = it & 1;
        for (int r = gw; r < BN; r += GW){
            int b = r >> 10;
            float eps = s_eps[b];
            float t[32];
            load_t(t, (const float4*)(d_C + ((size_t)r<<10)), lane, -L2E/eps);
            float at = -eps*LN2F*lse2(t, (const float4*)(d_ga + (b<<10)), lane);
            float bt = -eps*LN2F*lse2(t, (const float4*)(d_gb + (b<<10)), lane);
            if (lane == 0){
                float a0 = d_ay[r], b0 = d_bx[r];
                float a1 = 0.5f*(a0+at), b1 = 0.5f*(b0+bt);
                d_ay[r] = a1; d_bx[r] = b1;
                atomicMax(&d_dmax[p][b],    __float_as_uint(fabsf(a1-a0)));
                atomicMax(&d_dmax[p][BB+b], __float_as_uint(fabsf(b1-b0)));
            }
        }
        gsync();
    }

    for (int i = blockIdx.x*TPB+tid; i < BN; i += GT)
        d_ga[i] = (d_logw[i] + d_bx[i]*(1.f/EPSF))*L2E;
    gsync();
    for (int r = gw; r < BN; r += GW){
        int b = r >> 10;
        float t[32];
        load_t(t, (const float4*)(d_C + ((size_t)r<<10)), lane, -L2E/EPSF);
        float l = lse2(t, (const float4*)(d_ga + (b<<10)), lane);
        if (lane == 0) d_alpha[r] = -EPSF*LN2F*l;
    }
    gsync();
    for (int i = blockIdx.x*TPB+tid; i < BN; i += GT)
        d_ga[i] = d_alpha[i]*(L2E/EPSF);
    gsync();
    for (int r = gw; r < BN; r += GW){
        int b = r >> 10;
        float t[32];
        load_t(t, (const float4*)(d_C + ((size_t)r<<10)), lane, -L2E/EPSF);
        float M2 = lse2(t, (const float4*)(d_ga + (b<<10)), lane);
        if (lane == 0) d_gb[r] = (LOGNF + d_logw[r])*L2E - M2;
    }
}

// ---------------- K4: fused transport GEMM into f32 scratch -----------------
__global__ void k_out(const float* __restrict__ P){
    int b = blockIdx.y, i0 = blockIdx.x*64;
    int tid = threadIdx.x, tx = tid & 31, ty = tid >> 5;
    __shared__ float Ts[64][65];
    __shared__ float Ps[64][32];
    __shared__ float gls[64];
    float acc[8] = {};
    if (tid < 64) gls[tid] = d_ga[(b<<10) + i0 + tid];
    const float* Cb = d_C + ((size_t)b << 20);
    const float* Pb = P + ((size_t)b << 10)*DD;
    const float* r2b = d_gb + (b << 10);
    for (int j0 = 0; j0 < NN; j0 += 64){
        __syncthreads();
        for (int f = tid; f < 512; f += TPB){
            int row = f >> 3, c4 = f & 7;
            float4 v = ((const float4*)(Pb + (size_t)(j0+row)*DD))[c4];
            Ps[row][c4*4+0]=v.x; Ps[row][c4*4+1]=v.y; Ps[row][c4*4+2]=v.z; Ps[row][c4*4+3]=v.w;
        }
        for (int f = tid; f < 1024; f += TPB){
            int row = f >> 4, c4 = f & 15;
            float4 c = ((const float4*)(Cb + (size_t)(i0+row)*NN + j0))[c4];
            float4 r2 = ((const float4*)(r2b + j0))[c4];
            float gl = gls[row];
            int jj = c4*4;
            Ts[row][jj+0] = ex2(gl - c.x*(L2E/EPSF) + r2.x);
            Ts[row][jj+1] = ex2(gl - c.y*(L2E/EPSF) + r2.y);
            Ts[row][jj+2] = ex2(gl - c.z*(L2E/EPSF) + r2.z);
            Ts[row][jj+3] = ex2(gl - c.w*(L2E/EPSF) + r2.w);
        }
        __syncthreads();
#pragma unroll 8
        for (int jj = 0; jj < 64; jj++){
            float pv = Ps[jj][tx];
#pragma unroll
            for (int rr = 0; rr < 8; rr++)
                acc[rr] += Ts[ty*8+rr][jj] * pv;
        }
    }
#pragma unroll
    for (int rr = 0; rr < 8; rr++){
        int i = i0 + ty*8 + rr;
        d_res[((size_t)b*NN + i)*DD + tx] = acc[rr];
    }
}

// ---------------- K5: pack into d_out. FLOAT32 ONLY, fully guarded ----------
// Output assumed float32, 557056 elements (JAX promotion: x64 disabled makes
// index_p int32; concat(f32,f32,i32) -> f32). Every store is 4 bytes and
// guarded by i < out_size, so no overrun is possible for any dtype >= 4B.
__global__ void k_pack(float* __restrict__ o, int out_size){
    int i = blockIdx.x*TPB + threadIdx.x;
    if (i >= out_size) return;
    if (i < 524288)      o[i] = d_res[i];
    else if (i < 540672) o[i] = 1.0f/1024.0f;
    else if (i < 557056) o[i] = (float)(i - 540672);
}

extern "C" void kernel_launch(void* const* d_in, const int* in_sizes, int n_in,
                              void* d_out, int out_size){
    const float* P = (const float*)d_in[0];
    const float* W = (const float*)d_in[1];
    for (int i = 0; i < n_in; i++){
        if (in_sizes[i] == BN*DD) P = (const float*)d_in[i];
        else if (in_sizes[i] == BN) W = (const float*)d_in[i];
    }
    k_stats<<<BB, TPB>>>(P, W);
    k_cost<<<dim3(16,16,BB), TPB>>>();
    k_sink<<<NBLK, TPB>>>();
    k_out<<<dim3(16,BB), TPB>>>(P);
    k_pack<<<(out_size + TPB - 1)/TPB, TPB>>>((float*)d_out, out_size);
}

// round 17
// speedup vs baseline: 1.5007x; 1.5007x over previous
#include <cuda_runtime.h>

#define BB 16
#define NN 1024
#define DD 32
#define BN (BB*NN)
#define NBLK 296
#define TPB 256
#define L2E 1.4426950408889634f
#define LN2F 0.6931471805599453f
#define EPSF 0.1f
#define SFQ 0.5625f
#define THR 0.001f
#define LOGNF 6.9314718055994531f
#define CIR 14.426950408889634f   // L2E/EPSF

__device__ float d_C[(size_t)BB*NN*NN];
__device__ float d_sx[BB*NN*DD];
__device__ float d_x2[BN];
__device__ float d_logw[BN];
__device__ float d_lw2[BN];          // logw * log2e
__device__ float d_eps0[BB];
__device__ float d_pot[2][2*BN];     // [parity][ ay | bx ]
__device__ float d_gl[BN];           // alpha * log2e / eps
__device__ float d_r2[BN];           // column term for T
__device__ float d_res[BN*DD];
__device__ unsigned d_dmax[3][2*BB];
__device__ unsigned d_barcnt;
__device__ volatile unsigned d_bargen;

__device__ __forceinline__ float ex2(float x){ float r; asm("ex2.approx.ftz.f32 %0,%1;":"=f"(r):"f"(x)); return r; }
__device__ __forceinline__ float lg2(float x){ float r; asm("lg2.approx.f32 %0,%1;":"=f"(r):"f"(x)); return r; }

__device__ __forceinline__ void gsync(){
    __syncthreads();
    __threadfence();
    if (threadIdx.x == 0){
        unsigned gen = d_bargen;
        if (atomicAdd(&d_barcnt, 1u) == NBLK-1){
            d_barcnt = 0;
            __threadfence();
            d_bargen = gen + 1;
        } else {
            while (d_bargen == gen) __nanosleep(64);
        }
    }
    __syncthreads();
    __threadfence();
}

// ---------------- K1: per-batch stats, sx, x2, logw/lw2, eps0 ---------------
__global__ void k_stats(const float* __restrict__ P, const float* __restrict__ W){
    int b = blockIdx.x, tid = threadIdx.x;
    int d = tid & 31, g = tid >> 5;
    const float* Pb = P + (size_t)b*NN*DD;
    __shared__ float red[8][32];
    __shared__ float mean[32];
    __shared__ float s_inv;
    __shared__ float gmx[8], gmn[8];

    float s = 0.f;
    for (int n = g; n < NN; n += 8) s += Pb[n*DD + d];
    red[g][d] = s; __syncthreads();
    if (g == 0){
        float t = 0.f;
        for (int i = 0; i < 8; i++) t += red[i][d];
        mean[d] = t * (1.f/NN);
    }
    __syncthreads();
    float mu = mean[d];
    float q = 0.f;
    for (int n = g; n < NN; n += 8){ float c = Pb[n*DD+d]-mu; q += c*c; }
    __syncthreads();
    red[g][d] = q; __syncthreads();
    if (tid < 32){
        float t = 0.f;
        for (int i = 0; i < 8; i++) t += red[i][tid];
        float sd = sqrtf(t * (1.f/NN));
        for (int o = 16; o; o >>= 1) sd = fmaxf(sd, __shfl_xor_sync(0xffffffffu, sd, o));
        if (tid == 0){
            float diam = (sd == 0.f) ? 1.f : sd;
            s_inv = 1.f/(diam * sqrtf(32.f));
        }
    }
    __syncthreads();
    float inv = s_inv;
    float mx = -1e30f, mn = 1e30f;
    for (int n = g; n < NN; n += 8){
        float sx = (Pb[n*DD+d]-mu)*inv;
        d_sx[((size_t)b*NN+n)*DD + d] = sx;
        mx = fmaxf(mx, sx); mn = fminf(mn, sx);
        float sq = sx*sx;
        for (int o = 16; o; o >>= 1) sq += __shfl_xor_sync(0xffffffffu, sq, o);
        if (d == 0) d_x2[b*NN+n] = sq;
    }
    for (int o = 16; o; o >>= 1){
        mx = fmaxf(mx, __shfl_xor_sync(0xffffffffu, mx, o));
        mn = fminf(mn, __shfl_xor_sync(0xffffffffu, mn, o));
    }
    if (d == 0){ gmx[g] = mx; gmn[g] = mn; }
    __syncthreads();
    if (tid == 0){
        float a = gmx[0], c = gmn[0];
        for (int i = 1; i < 8; i++){ a = fmaxf(a,gmx[i]); c = fminf(c,gmn[i]); }
        float d2 = a - c;
        d_eps0[b] = d2*d2;
    }
    for (int i = tid; i < NN; i += TPB){
        float lw = logf(W[b*NN+i]);
        d_logw[b*NN+i] = lw;
        d_lw2[b*NN+i] = lw * L2E;
    }
}

// ---------------- K2: cost matrix (64x64 tiles) -----------------------------
__global__ void k_cost(){
    int b = blockIdx.z, ti = blockIdx.y*64, tj = blockIdx.x*64;
    __shared__ float As[64][33], Bs[64][33];
    __shared__ float Ax2[64], Bx2[64];
    int tid = threadIdx.x;
    const float* Sb = d_sx + (size_t)b*NN*DD;
    for (int f = tid; f < 512; f += TPB){
        int row = f >> 3, c4 = f & 7;
        float4 va = ((const float4*)(Sb + (size_t)(ti+row)*DD))[c4];
        As[row][c4*4+0]=va.x; As[row][c4*4+1]=va.y; As[row][c4*4+2]=va.z; As[row][c4*4+3]=va.w;
        float4 vb = ((const float4*)(Sb + (size_t)(tj+row)*DD))[c4];
        Bs[row][c4*4+0]=vb.x; Bs[row][c4*4+1]=vb.y; Bs[row][c4*4+2]=vb.z; Bs[row][c4*4+3]=vb.w;
    }
    if (tid < 64){ Ax2[tid] = d_x2[b*NN+ti+tid]; Bx2[tid] = d_x2[b*NN+tj+tid]; }
    __syncthreads();
    int tx = tid & 15, ty = tid >> 4;
    int i0 = ty*4, j0 = tx*4;
    float acc[4][4] = {};
#pragma unroll
    for (int k = 0; k < 32; k++){
        float a0=As[i0+0][k], a1=As[i0+1][k], a2=As[i0+2][k], a3=As[i0+3][k];
        float b0=Bs[j0+0][k], b1=Bs[j0+1][k], b2=Bs[j0+2][k], b3=Bs[j0+3][k];
        acc[0][0]+=a0*b0; acc[0][1]+=a0*b1; acc[0][2]+=a0*b2; acc[0][3]+=a0*b3;
        acc[1][0]+=a1*b0; acc[1][1]+=a1*b1; acc[1][2]+=a1*b2; acc[1][3]+=a1*b3;
        acc[2][0]+=a2*b0; acc[2][1]+=a2*b1; acc[2][2]+=a2*b2; acc[2][3]+=a2*b3;
        acc[3][0]+=a3*b0; acc[3][1]+=a3*b1; acc[3][2]+=a3*b2; acc[3][3]+=a3*b3;
    }
#pragma unroll
    for (int ii = 0; ii < 4; ii++){
        float xi = Ax2[i0+ii];
        float4 o;
        o.x = 0.5f*fmaxf(xi + Bx2[j0+0] - 2.f*acc[ii][0], 0.f);
        o.y = 0.5f*fmaxf(xi + Bx2[j0+1] - 2.f*acc[ii][1], 0.f);
        o.z = 0.5f*fmaxf(xi + Bx2[j0+2] - 2.f*acc[ii][2], 0.f);
        o.w = 0.5f*fmaxf(xi + Bx2[j0+3] - 2.f*acc[ii][3], 0.f);
        *(float4*)(d_C + ((size_t)(b*NN) + ti + i0 + ii)*NN + tj + j0) = o;
    }
}

// ---------------- K3: persistent Sinkhorn (1 barrier / iteration) -----------
__global__ void __launch_bounds__(TPB,2) k_sink(){
    __shared__ float s_eps[BB];
    __shared__ int s_glob[BB];
    __shared__ int s_stop;
    int tid = threadIdx.x, lane = tid & 31;
    int gw = blockIdx.x*8 + (tid >> 5);
    const int GW = NBLK*8;

    if (tid < BB) s_eps[tid] = d_eps0[tid];
    if (blockIdx.x == 0 && tid < 2*BB) d_dmax[0][tid] = 0u;
    __syncthreads();

    // ---- init: a_y0, b_x0 at eps0 -> parity 0 ----
    for (int r = gw; r < BN; r += GW){
        int b = r >> 10;
        float eps = s_eps[b];
        float ir = L2E/eps;
        const float4* c4 = (const float4*)(d_C + ((size_t)r<<10));
        const float4* w4 = (const float4*)(d_lw2 + (b<<10));
        float s1a=0,s1b=0,s1c=0,s1d=0, s2a=0,s2b=0,s2c=0,s2d=0;
#pragma unroll
        for (int u = 0; u < 8; u++){
            float4 c = c4[u*32+lane];
            float4 w = w4[u*32+lane];
            float tx = -c.x*ir, ty = -c.y*ir, tz = -c.z*ir, tw = -c.w*ir;
            s1a += ex2(w.x+tx); s1b += ex2(w.y+ty); s1c += ex2(w.z+tz); s1d += ex2(w.w+tw);
            s2a += ex2(tx);     s2b += ex2(ty);     s2c += ex2(tz);     s2d += ex2(tw);
        }
        float s1 = (s1a+s1b)+(s1c+s1d), s2 = (s2a+s2b)+(s2c+s2d);
#pragma unroll
        for (int o = 16; o; o >>= 1){
            s1 += __shfl_xor_sync(0xffffffffu, s1, o);
            s2 += __shfl_xor_sync(0xffffffffu, s2, o);
        }
        if (lane == 0){
            d_pot[0][r]    = -eps*LN2F*lg2(s1);
            d_pot[0][BN+r] = -eps*LN2F*(lg2(s2) - 10.0f);
        }
    }
    gsync();

    int fp = 0;
    for (int it = 0; it < 99; ++it){
        if (it > 0){
            if (tid < BB){
                int pp = (it-1) % 3;
                float da = __uint_as_float(d_dmax[pp][tid]);
                float db = __uint_as_float(d_dmax[pp][BB+tid]);
                float re = s_eps[tid];
                float ne = fmaxf(re*SFQ, EPSF);
                s_glob[tid] = (ne < re) || (da > THR) || (db > THR);
                s_eps[tid] = ne;
            }
            __syncthreads();
            if (tid == 0){
                int st = 0;
                for (int i = 0; i < BB; i++) if (!s_glob[i]) st = 1;
                s_stop = st;
            }
            __syncthreads();
            if (s_stop) break;
        }
        if (blockIdx.x == 0 && tid < 2*BB) d_dmax[(it+1)%3][tid] = 0u;

        int p = fp, q = 1 - fp;
        unsigned* dm = d_dmax[it % 3];
        for (int r = gw; r < BN; r += GW){
            int b = r >> 10;
            float eps = s_eps[b];
            float ir = L2E/eps;
            const float4* c4 = (const float4*)(d_C + ((size_t)r<<10));
            const float4* w4 = (const float4*)(d_lw2 + (b<<10));
            const float4* a4 = (const float4*)(d_pot[p] + (b<<10));
            const float4* b4 = (const float4*)(d_pot[p] + BN + (b<<10));
            float s1a=0,s1b=0,s1c=0,s1d=0, s2a=0,s2b=0,s2c=0,s2d=0;
#pragma unroll
            for (int u = 0; u < 8; u++){
                float4 c = c4[u*32+lane];
                float4 w = w4[u*32+lane];
                float4 av = a4[u*32+lane];
                float4 bv = b4[u*32+lane];
                s1a += ex2(fmaf(bv.x - c.x, ir, w.x));
                s1b += ex2(fmaf(bv.y - c.y, ir, w.y));
                s1c += ex2(fmaf(bv.z - c.z, ir, w.z));
                s1d += ex2(fmaf(bv.w - c.w, ir, w.w));
                s2a += ex2(fmaf(av.x - c.x, ir, -10.0f));
                s2b += ex2(fmaf(av.y - c.y, ir, -10.0f));
                s2c += ex2(fmaf(av.z - c.z, ir, -10.0f));
                s2d += ex2(fmaf(av.w - c.w, ir, -10.0f));
            }
            float s1 = (s1a+s1b)+(s1c+s1d), s2 = (s2a+s2b)+(s2c+s2d);
#pragma unroll
            for (int o = 16; o; o >>= 1){
                s1 += __shfl_xor_sync(0xffffffffu, s1, o);
                s2 += __shfl_xor_sync(0xffffffffu, s2, o);
            }
            if (lane == 0){
                float at = -eps*LN2F*lg2(s1);
                float bt = -eps*LN2F*lg2(s2);
                float a0 = d_pot[p][r], b0 = d_pot[p][BN+r];
                float a1 = 0.5f*(a0+at), b1 = 0.5f*(b0+bt);
                d_pot[q][r] = a1; d_pot[q][BN+r] = b1;
                atomicMax(&dm[b],    __float_as_uint(fabsf(a1-a0)));
                atomicMax(&dm[BB+b], __float_as_uint(fabsf(b1-b0)));
            }
        }
        fp = q;
        gsync();
    }

    // ---- final alpha at EPS, and gl = alpha*L2E/EPS ----
    for (int r = gw; r < BN; r += GW){
        int b = r >> 10;
        const float4* c4 = (const float4*)(d_C + ((size_t)r<<10));
        const float4* w4 = (const float4*)(d_lw2 + (b<<10));
        const float4* b4 = (const float4*)(d_pot[fp] + BN + (b<<10));
        float sa=0,sb=0,sc=0,sd=0;
#pragma unroll
        for (int u = 0; u < 8; u++){
            float4 c = c4[u*32+lane];
            float4 w = w4[u*32+lane];
            float4 bv = b4[u*32+lane];
            sa += ex2(fmaf(bv.x - c.x, CIR, w.x));
            sb += ex2(fmaf(bv.y - c.y, CIR, w.y));
            sc += ex2(fmaf(bv.z - c.z, CIR, w.z));
            sd += ex2(fmaf(bv.w - c.w, CIR, w.w));
        }
        float s = (sa+sb)+(sc+sd);
#pragma unroll
        for (int o = 16; o; o >>= 1) s += __shfl_xor_sync(0xffffffffu, s, o);
        if (lane == 0){
            float alpha = -EPSF*LN2F*lg2(s);
            d_gl[r] = alpha*CIR;
        }
    }
    gsync();
    // ---- column term: r2_j = (logN + logw_j)*L2E - lse2_i(gl_i - C_ij*CIR) ----
    for (int r = gw; r < BN; r += GW){
        int b = r >> 10;
        const float4* c4 = (const float4*)(d_C + ((size_t)r<<10));
        const float4* g4 = (const float4*)(d_gl + (b<<10));
        float sa=0,sb=0,sc=0,sd=0;
#pragma unroll
        for (int u = 0; u < 8; u++){
            float4 c = c4[u*32+lane];
            float4 g = g4[u*32+lane];
            sa += ex2(fmaf(c.x, -CIR, g.x));
            sb += ex2(fmaf(c.y, -CIR, g.y));
            sc += ex2(fmaf(c.z, -CIR, g.z));
            sd += ex2(fmaf(c.w, -CIR, g.w));
        }
        float s = (sa+sb)+(sc+sd);
#pragma unroll
        for (int o = 16; o; o >>= 1) s += __shfl_xor_sync(0xffffffffu, s, o);
        if (lane == 0) d_r2[r] = (LOGNF + d_logw[r])*L2E - lg2(s);
    }
}

// ---------------- K4: fused transport GEMM with C-tile prefetch -------------
__global__ void k_out(const float* __restrict__ P){
    int b = blockIdx.y, i0 = blockIdx.x*64;
    int tid = threadIdx.x, tx = tid & 31, ty = tid >> 5;
    __shared__ float Ts[64][65];
    __shared__ float Ps[64][32];
    __shared__ float gls[64];
    float acc[8] = {};
    if (tid < 64) gls[tid] = d_gl[(b<<10) + i0 + tid];
    const float* Cb = d_C + ((size_t)b << 20);
    const float* Pb = P + ((size_t)b << 10)*DD;
    const float* r2b = d_r2 + (b << 10);

    int frow[4], fc4[4], prow[2], pc4[2];
#pragma unroll
    for (int k = 0; k < 4; k++){ int f = tid + k*TPB; frow[k] = f >> 4; fc4[k] = f & 15; }
#pragma unroll
    for (int k = 0; k < 2; k++){ int f = tid + k*TPB; prow[k] = f >> 3; pc4[k] = f & 7; }

    float4 cp[4], rp[4], pp[2];
#pragma unroll
    for (int k = 0; k < 4; k++){
        cp[k] = ((const float4*)(Cb + (size_t)(i0+frow[k])*NN))[fc4[k]];
        rp[k] = ((const float4*)r2b)[fc4[k]];
    }
#pragma unroll
    for (int k = 0; k < 2; k++)
        pp[k] = ((const float4*)(Pb + (size_t)prow[k]*DD))[pc4[k]];
    __syncthreads();

    for (int j0 = 0; j0 < NN; j0 += 64){
#pragma unroll
        for (int k = 0; k < 2; k++){
            Ps[prow[k]][pc4[k]*4+0] = pp[k].x; Ps[prow[k]][pc4[k]*4+1] = pp[k].y;
            Ps[prow[k]][pc4[k]*4+2] = pp[k].z; Ps[prow[k]][pc4[k]*4+3] = pp[k].w;
        }
#pragma unroll
        for (int k = 0; k < 4; k++){
            float gl = gls[frow[k]];
            int jj = fc4[k]*4;
            Ts[frow[k]][jj+0] = ex2(fmaf(cp[k].x, -CIR, gl + rp[k].x));
            Ts[frow[k]][jj+1] = ex2(fmaf(cp[k].y, -CIR, gl + rp[k].y));
            Ts[frow[k]][jj+2] = ex2(fmaf(cp[k].z, -CIR, gl + rp[k].z));
            Ts[frow[k]][jj+3] = ex2(fmaf(cp[k].w, -CIR, gl + rp[k].w));
        }
        __syncthreads();
        if (j0 + 64 < NN){
            int jn = j0 + 64;
#pragma unroll
            for (int k = 0; k < 4; k++){
                cp[k] = ((const float4*)(Cb + (size_t)(i0+frow[k])*NN + jn))[fc4[k]];
                rp[k] = ((const float4*)(r2b + jn))[fc4[k]];
            }
#pragma unroll
            for (int k = 0; k < 2; k++)
                pp[k] = ((const float4*)(Pb + (size_t)(jn+prow[k])*DD))[pc4[k]];
        }
#pragma unroll 8
        for (int jj = 0; jj < 64; jj++){
            float pv = Ps[jj][tx];
#pragma unroll
            for (int rr = 0; rr < 8; rr++)
                acc[rr] += Ts[ty*8+rr][jj] * pv;
        }
        __syncthreads();
    }
#pragma unroll
    for (int rr = 0; rr < 8; rr++){
        int i = i0 + ty*8 + rr;
        d_res[((size_t)b*NN + i)*DD + tx] = acc[rr];
    }
}

// ---------------- K5: pack (float32 output, fully guarded) ------------------
__global__ void k_pack(float* __restrict__ o, int out_size){
    int i = blockIdx.x*TPB + threadIdx.x;
    if (i >= out_size) return;
    if (i < 524288)      o[i] = d_res[i];
    else if (i < 540672) o[i] = 1.0f/1024.0f;
    else if (i < 557056) o[i] = (float)(i - 540672);
}

extern "C" void kernel_launch(void* const* d_in, const int* in_sizes, int n_in,
                              void* d_out, int out_size){
    const float* P = (const float*)d_in[0];
    const float* W = (const float*)d_in[1];
    for (int i = 0; i < n_in; i++){
        if (in_sizes[i] == BN*DD) P = (const float*)d_in[i];
        else if (in_sizes[i] == BN) W = (const float*)d_in[i];
    }
    k_stats<<<BB, TPB>>>(P, W);
    k_cost<<<dim3(16,16,BB), TPB>>>();
    k_sink<<<NBLK, TPB>>>();
    k_out<<<dim3(16,BB), TPB>>>(P);
    k_pack<<<(out_size + TPB - 1)/TPB, TPB>>>((float*)d_out, out_size);
}